// round 8
// baseline (speedup 1.0000x reference)
#include <cuda_runtime.h>
#include <cstdint>

#define L_LEN   65536
#define L_MASK  (L_LEN - 1)
#define CIN     8
#define COUT    8
#define FS      4
#define TPB     128
#define TILE    1024
#define ROWF    1028       // 1024 + 4 halo floats, 16B-aligned row stride

// ---- packed f32x2 helpers (Blackwell sm_100a+) ------------------------------
__device__ __forceinline__ float2 ffma2(float2 a, float2 b, float2 c) {
    float2 d;
    asm("fma.rn.f32x2 %0, %1, %2, %3;"
        : "=l"(reinterpret_cast<unsigned long long&>(d))
        : "l"(reinterpret_cast<const unsigned long long&>(a)),
          "l"(reinterpret_cast<const unsigned long long&>(b)),
          "l"(reinterpret_cast<const unsigned long long&>(c)));
    return d;
}

__device__ __forceinline__ float2 dup2(float x) {
    float2 d;
    asm("mov.b64 %0, {%1, %1};"
        : "=l"(reinterpret_cast<unsigned long long&>(d))
        : "f"(x));
    return d;
}

__device__ __forceinline__ uint32_t smem_u32(const void* p) {
    uint32_t a;
    asm("{ .reg .u64 t; cvta.to.shared.u64 t, %1; cvt.u32.u64 %0, t; }"
        : "=r"(a) : "l"(p));
    return a;
}

__device__ __forceinline__ void cp_async16(uint32_t dst, const float* src) {
    asm volatile("cp.async.cg.shared.global [%0], [%1], 16;"
                 :: "r"(dst), "l"(src));
}

// ----------------------------------------------------------------------------
// out[b, co, l] = bias[co] + sum_{ci,k} x[b, ci, (l+k) mod L] * W[co, ci, k]
//
// R4 structure (one-shot block, 1024 positions, single barrier, monolithic
// compute) with two register cuts:
//   - staging via cp.async (one commit, one wait, one barrier)
//   - compute split into two co-halves (acc 32 regs instead of 64)
// Thread t owns bundles at 4t and 4t+512: conflict-free LDS.128 windows,
// perfectly coalesced STG.128 stores.
// ----------------------------------------------------------------------------
__global__ __launch_bounds__(TPB, 6)
void conv_pbc_kernel(const float* __restrict__ x,
                     const float* __restrict__ W,
                     const float* __restrict__ bias,
                     float* __restrict__ out)
{
    __shared__ float  xs[CIN][ROWF];
    __shared__ float2 w2s[CIN][FS][COUT / 2];   // (W[2p,ci,k], W[2p+1,ci,k])
    __shared__ float2 b2s[COUT / 2];

    const int t = threadIdx.x;

    // ---- weights / bias into SMEM (128 packed entries, one per thread) ----
    {
        const int cp = t & 3;
        const int k  = (t >> 2) & 3;
        const int ci = (t >> 4) & 7;
        w2s[ci][k][cp] = make_float2(W[(2 * cp)     * CIN * FS + ci * FS + k],
                                     W[(2 * cp + 1) * CIN * FS + ci * FS + k]);
    }
    if (t < COUT / 2)
        b2s[t] = make_float2(bias[2 * t], bias[2 * t + 1]);

    const int b    = blockIdx.x >> 6;          // 64 chunks per batch
    const int base = (blockIdx.x & 63) << 10;  // chunk * 1024

    const float* __restrict__ xb = x + (size_t)b * CIN * L_LEN;
    const uint32_t xs_base = smem_u32(&xs[0][0]);

    // ---- one-shot staging: 17 cp.asyncs in flight, single wait ----
    #pragma unroll
    for (int ci = 0; ci < CIN; ++ci) {
        const float* __restrict__ xc = xb + (size_t)ci * L_LEN + base;
        const uint32_t dst = xs_base + ci * (ROWF * 4);
        cp_async16(dst + 16u * t,           xc + 4 * t);
        cp_async16(dst + 2048u + 16u * t,   xc + 512 + 4 * t);
    }
    if (t < CIN)   // halo: 4 floats past the tile, circular (16B aligned)
        cp_async16(xs_base + t * (ROWF * 4) + TILE * 4,
                   xb + (size_t)t * L_LEN + ((base + TILE) & L_MASK));
    asm volatile("cp.async.commit_group;");
    asm volatile("cp.async.wait_group 0;");
    __syncthreads();                           // tile + weights resident

    float* __restrict__ ob = out + (size_t)b * COUT * L_LEN + base + 4 * t;

    // ---- compute: two co-halves, each 4 output channels ----
    #pragma unroll
    for (int half = 0; half < 2; ++half) {
        // acc[bundle][q][cpl] for co pairs p = 2*half + cpl
        float2 acc[2][4][2];
        {
            const float2 c0 = b2s[2 * half], c1 = b2s[2 * half + 1];
            #pragma unroll
            for (int j = 0; j < 2; ++j)
                #pragma unroll
                for (int q = 0; q < 4; ++q) {
                    acc[j][q][0] = c0; acc[j][q][1] = c1;
                }
        }

        #pragma unroll
        for (int ci = 0; ci < CIN; ++ci) {
            float2 wv[FS][2];
            #pragma unroll
            for (int k = 0; k < FS; ++k) {
                wv[k][0] = w2s[ci][k][2 * half];
                wv[k][1] = w2s[ci][k][2 * half + 1];
            }

            float xw[2][8];
            {
                const float4 a0 = *reinterpret_cast<const float4*>(&xs[ci][4 * t]);
                const float4 a1 = *reinterpret_cast<const float4*>(&xs[ci][4 * t + 4]);
                const float4 b0 = *reinterpret_cast<const float4*>(&xs[ci][512 + 4 * t]);
                const float4 b1 = *reinterpret_cast<const float4*>(&xs[ci][512 + 4 * t + 4]);
                xw[0][0] = a0.x; xw[0][1] = a0.y; xw[0][2] = a0.z; xw[0][3] = a0.w;
                xw[0][4] = a1.x; xw[0][5] = a1.y; xw[0][6] = a1.z; xw[0][7] = a1.w;
                xw[1][0] = b0.x; xw[1][1] = b0.y; xw[1][2] = b0.z; xw[1][3] = b0.w;
                xw[1][4] = b1.x; xw[1][5] = b1.y; xw[1][6] = b1.z; xw[1][7] = b1.w;
            }

            #pragma unroll
            for (int j = 0; j < 2; ++j) {
                #pragma unroll
                for (int i = 0; i < 7; ++i) {
                    const float2 xk = dup2(xw[j][i]);
                    #pragma unroll
                    for (int k = 0; k < FS; ++k) {
                        const int q = i - k;
                        if (q >= 0 && q < 4) {
                            acc[j][q][0] = ffma2(wv[k][0], xk, acc[j][q][0]);
                            acc[j][q][1] = ffma2(wv[k][1], xk, acc[j][q][1]);
                        }
                    }
                }
            }
        }

        // ---- store this half's 4 channels (coalesced STG.128) ----
        #pragma unroll
        for (int cpl = 0; cpl < 2; ++cpl) {
            const int p = 2 * half + cpl;          // co pair (2p, 2p+1)
            #pragma unroll
            for (int j = 0; j < 2; ++j) {
                float4 v;
                v.x = acc[j][0][cpl].x; v.y = acc[j][1][cpl].x;
                v.z = acc[j][2][cpl].x; v.w = acc[j][3][cpl].x;
                *reinterpret_cast<float4*>(ob + (size_t)(2 * p) * L_LEN + 512 * j) = v;
                v.x = acc[j][0][cpl].y; v.y = acc[j][1][cpl].y;
                v.z = acc[j][2][cpl].y; v.w = acc[j][3][cpl].y;
                *reinterpret_cast<float4*>(ob + (size_t)(2 * p + 1) * L_LEN + 512 * j) = v;
            }
        }
    }
}

extern "C" void kernel_launch(void* const* d_in, const int* in_sizes, int n_in,
                              void* d_out, int out_size)
{
    const float* x    = (const float*)d_in[0];  // (64, 8, 65536)
    const float* W    = (const float*)d_in[1];  // (8, 8, 4)
    const float* bias = (const float*)d_in[2];  // (8,)
    float* out        = (float*)d_out;          // (64, 8, 65536)

    // 64 batches * 64 position-chunks = 4096 blocks of 128
    conv_pbc_kernel<<<64 * (L_LEN / TILE), TPB>>>(x, W, bias, out);
}

// round 9
// speedup vs baseline: 1.2678x; 1.2678x over previous
#include <cuda_runtime.h>
#include <cstdint>

#define L_LEN   65536
#define L_MASK  (L_LEN - 1)
#define CIN     8
#define COUT    8
#define FS      4
#define TPB     128
#define TILE    1024
#define ROWF    1028       // 1024 + 4 halo floats, 16B-aligned row stride

// ---- packed f32x2 helpers (Blackwell sm_100a+) ------------------------------
__device__ __forceinline__ float2 ffma2(float2 a, float2 b, float2 c) {
    float2 d;
    asm("fma.rn.f32x2 %0, %1, %2, %3;"
        : "=l"(reinterpret_cast<unsigned long long&>(d))
        : "l"(reinterpret_cast<const unsigned long long&>(a)),
          "l"(reinterpret_cast<const unsigned long long&>(b)),
          "l"(reinterpret_cast<const unsigned long long&>(c)));
    return d;
}

__device__ __forceinline__ float2 dup2(float x) {
    float2 d;
    asm("mov.b64 %0, {%1, %1};"
        : "=l"(reinterpret_cast<unsigned long long&>(d))
        : "f"(x));
    return d;
}

__device__ __forceinline__ uint32_t smem_u32(const void* p) {
    uint32_t a;
    asm("{ .reg .u64 t; cvta.to.shared.u64 t, %1; cvt.u32.u64 %0, t; }"
        : "=r"(a) : "l"(p));
    return a;
}

__device__ __forceinline__ void cp_async16(uint32_t dst, const float* src) {
    asm volatile("cp.async.cg.shared.global [%0], [%1], 16;"
                 :: "r"(dst), "l"(src));
}

// ----------------------------------------------------------------------------
// out[b, co, l] = bias[co] + sum_{ci,k} x[b, ci, (l+k) mod L] * W[co, ci, k]
//
// One-shot block over 1024 positions: cp.async stages the full x tile with a
// single commit/wait/barrier, then two monolithic co-half compute passes
// (4 output channels each, acc = 32 regs) run back-to-back with no further
// syncs. __launch_bounds__(128, 5) = 96-reg cap, which the kernel fits
// WITHOUT spilling (R8's 80-reg cap caused local-memory spills: 2x DRAM
// traffic, 2x duration). Thread t owns bundles at 4t and 4t+512:
// conflict-free LDS.128 windows, perfectly coalesced STG.128 stores.
// ----------------------------------------------------------------------------
__global__ __launch_bounds__(TPB, 5)
void conv_pbc_kernel(const float* __restrict__ x,
                     const float* __restrict__ W,
                     const float* __restrict__ bias,
                     float* __restrict__ out)
{
    __shared__ float  xs[CIN][ROWF];
    __shared__ float2 w2s[CIN][FS][COUT / 2];   // (W[2p,ci,k], W[2p+1,ci,k])
    __shared__ float2 b2s[COUT / 2];

    const int t = threadIdx.x;

    // ---- weights / bias into SMEM (128 packed entries, one per thread) ----
    {
        const int cp = t & 3;
        const int k  = (t >> 2) & 3;
        const int ci = (t >> 4) & 7;
        w2s[ci][k][cp] = make_float2(W[(2 * cp)     * CIN * FS + ci * FS + k],
                                     W[(2 * cp + 1) * CIN * FS + ci * FS + k]);
    }
    if (t < COUT / 2)
        b2s[t] = make_float2(bias[2 * t], bias[2 * t + 1]);

    const int b    = blockIdx.x >> 6;          // 64 chunks per batch
    const int base = (blockIdx.x & 63) << 10;  // chunk * 1024

    const float* __restrict__ xb = x + (size_t)b * CIN * L_LEN;
    const uint32_t xs_base = smem_u32(&xs[0][0]);

    // ---- one-shot staging: 17 cp.asyncs in flight, single wait ----
    #pragma unroll
    for (int ci = 0; ci < CIN; ++ci) {
        const float* __restrict__ xc = xb + (size_t)ci * L_LEN + base;
        const uint32_t dst = xs_base + ci * (ROWF * 4);
        cp_async16(dst + 16u * t,           xc + 4 * t);
        cp_async16(dst + 2048u + 16u * t,   xc + 512 + 4 * t);
    }
    if (t < CIN)   // halo: 4 floats past the tile, circular (16B aligned)
        cp_async16(xs_base + t * (ROWF * 4) + TILE * 4,
                   xb + (size_t)t * L_LEN + ((base + TILE) & L_MASK));
    asm volatile("cp.async.commit_group;");
    asm volatile("cp.async.wait_group 0;");
    __syncthreads();                           // tile + weights resident

    float* __restrict__ ob = out + (size_t)b * COUT * L_LEN + base + 4 * t;

    // ---- compute: two co-halves, each 4 output channels ----
    #pragma unroll
    for (int half = 0; half < 2; ++half) {
        // acc[bundle][q][cpl] for co pairs p = 2*half + cpl
        float2 acc[2][4][2];
        {
            const float2 c0 = b2s[2 * half], c1 = b2s[2 * half + 1];
            #pragma unroll
            for (int j = 0; j < 2; ++j)
                #pragma unroll
                for (int q = 0; q < 4; ++q) {
                    acc[j][q][0] = c0; acc[j][q][1] = c1;
                }
        }

        #pragma unroll
        for (int ci = 0; ci < CIN; ++ci) {
            float2 wv[FS][2];
            #pragma unroll
            for (int k = 0; k < FS; ++k) {
                wv[k][0] = w2s[ci][k][2 * half];
                wv[k][1] = w2s[ci][k][2 * half + 1];
            }

            float xw[2][8];
            {
                const float4 a0 = *reinterpret_cast<const float4*>(&xs[ci][4 * t]);
                const float4 a1 = *reinterpret_cast<const float4*>(&xs[ci][4 * t + 4]);
                const float4 b0 = *reinterpret_cast<const float4*>(&xs[ci][512 + 4 * t]);
                const float4 b1 = *reinterpret_cast<const float4*>(&xs[ci][512 + 4 * t + 4]);
                xw[0][0] = a0.x; xw[0][1] = a0.y; xw[0][2] = a0.z; xw[0][3] = a0.w;
                xw[0][4] = a1.x; xw[0][5] = a1.y; xw[0][6] = a1.z; xw[0][7] = a1.w;
                xw[1][0] = b0.x; xw[1][1] = b0.y; xw[1][2] = b0.z; xw[1][3] = b0.w;
                xw[1][4] = b1.x; xw[1][5] = b1.y; xw[1][6] = b1.z; xw[1][7] = b1.w;
            }

            #pragma unroll
            for (int j = 0; j < 2; ++j) {
                #pragma unroll
                for (int i = 0; i < 7; ++i) {
                    const float2 xk = dup2(xw[j][i]);
                    #pragma unroll
                    for (int k = 0; k < FS; ++k) {
                        const int q = i - k;
                        if (q >= 0 && q < 4) {
                            acc[j][q][0] = ffma2(wv[k][0], xk, acc[j][q][0]);
                            acc[j][q][1] = ffma2(wv[k][1], xk, acc[j][q][1]);
                        }
                    }
                }
            }
        }

        // ---- store this half's 4 channels (coalesced STG.128) ----
        #pragma unroll
        for (int cpl = 0; cpl < 2; ++cpl) {
            const int p = 2 * half + cpl;          // co pair (2p, 2p+1)
            #pragma unroll
            for (int j = 0; j < 2; ++j) {
                float4 v;
                v.x = acc[j][0][cpl].x; v.y = acc[j][1][cpl].x;
                v.z = acc[j][2][cpl].x; v.w = acc[j][3][cpl].x;
                *reinterpret_cast<float4*>(ob + (size_t)(2 * p) * L_LEN + 512 * j) = v;
                v.x = acc[j][0][cpl].y; v.y = acc[j][1][cpl].y;
                v.z = acc[j][2][cpl].y; v.w = acc[j][3][cpl].y;
                *reinterpret_cast<float4*>(ob + (size_t)(2 * p + 1) * L_LEN + 512 * j) = v;
            }
        }
    }
}

extern "C" void kernel_launch(void* const* d_in, const int* in_sizes, int n_in,
                              void* d_out, int out_size)
{
    const float* x    = (const float*)d_in[0];  // (64, 8, 65536)
    const float* W    = (const float*)d_in[1];  // (8, 8, 4)
    const float* bias = (const float*)d_in[2];  // (8,)
    float* out        = (float*)d_out;          // (64, 8, 65536)

    // 64 batches * 64 position-chunks = 4096 blocks of 128
    conv_pbc_kernel<<<64 * (L_LEN / TILE), TPB>>>(x, W, bias, out);
}

// round 10
// speedup vs baseline: 2.0787x; 1.6396x over previous
#include <cuda_runtime.h>
#include <cstdint>

#define L_LEN   65536
#define L_MASK  (L_LEN - 1)
#define CIN     8
#define COUT    8
#define FS      4
#define TPB     128
#define TILE    1024            // positions per block
#define ROWF    1028            // smem row floats (1024 + 4 halo), 16B-aligned

// ---- packed f32x2 helpers (Blackwell sm_100a+) ------------------------------
__device__ __forceinline__ float2 ffma2(float2 a, float2 b, float2 c) {
    float2 d;
    asm("fma.rn.f32x2 %0, %1, %2, %3;"
        : "=l"(reinterpret_cast<unsigned long long&>(d))
        : "l"(reinterpret_cast<const unsigned long long&>(a)),
          "l"(reinterpret_cast<const unsigned long long&>(b)),
          "l"(reinterpret_cast<const unsigned long long&>(c)));
    return d;
}

__device__ __forceinline__ float2 dup2(float x) {
    float2 d;
    asm("mov.b64 %0, {%1, %1};"
        : "=l"(reinterpret_cast<unsigned long long&>(d))
        : "f"(x));
    return d;
}

__device__ __forceinline__ uint32_t smem_u32(const void* p) {
    uint32_t a;
    asm("{ .reg .u64 t; cvta.to.shared.u64 t, %1; cvt.u32.u64 %0, t; }"
        : "=r"(a) : "l"(p));
    return a;
}

__device__ __forceinline__ void cp_async16(uint32_t dst, const float* src) {
    asm volatile("cp.async.cg.shared.global [%0], [%1], 16;"
                 :: "r"(dst), "l"(src));
}

// ----------------------------------------------------------------------------
// out[b, co, l] = bias[co] + sum_{ci,k} x[b, ci, (l+k) mod L] * W[co, ci, k]
//
// R4 (best: 48.6us, 118 regs, no spill) with ONE change: staging via cp.async
// in the identical single-commit / single-wait / single-barrier shape —
// removes the 32 LDG + 17 STS prologue and its 68-register live range.
// Block: one batch b, 1024 positions, all ci staged in SMEM, then one
// monolithic compute phase. Thread t owns two 4-position bundles at 4t and
// 4t+512 -> conflict-free LDS.128 windows, coalesced STG.128 epilogue.
// ----------------------------------------------------------------------------
__global__ __launch_bounds__(TPB, 4)
void conv_pbc_kernel(const float* __restrict__ x,
                     const float* __restrict__ W,
                     const float* __restrict__ bias,
                     float* __restrict__ out)
{
    __shared__ float  xs[CIN][ROWF];
    __shared__ float2 w2s[CIN][FS][COUT / 2];   // (W[2cp,ci,k], W[2cp+1,ci,k])
    __shared__ float2 b2s[COUT / 2];

    const int t = threadIdx.x;

    // ---- weights / bias into SMEM (128 packed entries, one per thread) ----
    {
        const int cp = t & 3;
        const int k  = (t >> 2) & 3;
        const int ci = (t >> 4) & 7;
        w2s[ci][k][cp] = make_float2(W[(2 * cp)     * CIN * FS + ci * FS + k],
                                     W[(2 * cp + 1) * CIN * FS + ci * FS + k]);
    }
    if (t < COUT / 2)
        b2s[t] = make_float2(bias[2 * t], bias[2 * t + 1]);

    const int b    = blockIdx.x >> 6;          // 64 chunks per batch
    const int base = (blockIdx.x & 63) << 10;  // chunk * 1024

    const float* __restrict__ xb = x + (size_t)b * CIN * L_LEN;
    const uint32_t xs_base = smem_u32(&xs[0][0]);

    // ---- phase 1: stage x tile via cp.async (17 in flight, single wait) ----
    #pragma unroll
    for (int ci = 0; ci < CIN; ++ci) {
        const float* __restrict__ xc = xb + (size_t)ci * L_LEN + base;
        const uint32_t dst = xs_base + ci * (ROWF * 4);
        cp_async16(dst + 16u * t,         xc + 4 * t);
        cp_async16(dst + 2048u + 16u * t, xc + 512 + 4 * t);
    }
    if (t < CIN)   // halo: 4 floats past the tile, circular (always aligned)
        cp_async16(xs_base + t * (ROWF * 4) + TILE * 4,
                   xb + (size_t)t * L_LEN + ((base + TILE) & L_MASK));
    asm volatile("cp.async.commit_group;");
    asm volatile("cp.async.wait_group 0;");
    __syncthreads();                           // tile + weights resident

    // ---- accumulators: acc[bundle][q][cp], init = bias ----
    float2 acc[2][4][COUT / 2];
    {
        const float2 c0 = b2s[0], c1 = b2s[1], c2 = b2s[2], c3 = b2s[3];
        #pragma unroll
        for (int j = 0; j < 2; ++j)
            #pragma unroll
            for (int q = 0; q < 4; ++q) {
                acc[j][q][0] = c0; acc[j][q][1] = c1;
                acc[j][q][2] = c2; acc[j][q][3] = c3;
            }
    }

    // ---- phase 2: monolithic compute from SMEM (identical to R4) ----
    #pragma unroll
    for (int ci = 0; ci < CIN; ++ci) {
        // packed weights for this ci (broadcast LDS, conflict-free)
        float2 wv[FS][COUT / 2];
        #pragma unroll
        for (int k = 0; k < FS; ++k)
            #pragma unroll
            for (int cp = 0; cp < 4; ++cp)
                wv[k][cp] = w2s[ci][k][cp];

        // two 8-float windows, each two conflict-free LDS.128
        float xw[2][8];
        {
            const float4 a0 = *reinterpret_cast<const float4*>(&xs[ci][4 * t]);
            const float4 a1 = *reinterpret_cast<const float4*>(&xs[ci][4 * t + 4]);
            const float4 b0 = *reinterpret_cast<const float4*>(&xs[ci][512 + 4 * t]);
            const float4 b1 = *reinterpret_cast<const float4*>(&xs[ci][512 + 4 * t + 4]);
            xw[0][0] = a0.x; xw[0][1] = a0.y; xw[0][2] = a0.z; xw[0][3] = a0.w;
            xw[0][4] = a1.x; xw[0][5] = a1.y; xw[0][6] = a1.z; xw[0][7] = a1.w;
            xw[1][0] = b0.x; xw[1][1] = b0.y; xw[1][2] = b0.z; xw[1][3] = b0.w;
            xw[1][4] = b1.x; xw[1][5] = b1.y; xw[1][6] = b1.z; xw[1][7] = b1.w;
        }

        // dup2 each window value once; fan out to all (q, k) with q = i - k
        #pragma unroll
        for (int j = 0; j < 2; ++j) {
            #pragma unroll
            for (int i = 0; i < 7; ++i) {
                const float2 xk = dup2(xw[j][i]);
                #pragma unroll
                for (int k = 0; k < FS; ++k) {
                    const int q = i - k;
                    if (q >= 0 && q < 4) {
                        #pragma unroll
                        for (int cp = 0; cp < 4; ++cp)
                            acc[j][q][cp] = ffma2(wv[k][cp], xk, acc[j][q][cp]);
                    }
                }
            }
        }
    }

    // ---- epilogue: coalesced STG.128 per (co, bundle) ----
    float* __restrict__ ob = out + (size_t)b * COUT * L_LEN + base;
    #pragma unroll
    for (int cp = 0; cp < 4; ++cp) {
        #pragma unroll
        for (int j = 0; j < 2; ++j) {
            float4 v;
            v.x = acc[j][0][cp].x; v.y = acc[j][1][cp].x;
            v.z = acc[j][2][cp].x; v.w = acc[j][3][cp].x;
            *reinterpret_cast<float4*>(ob + (size_t)(2 * cp) * L_LEN + 512 * j + 4 * t) = v;
            v.x = acc[j][0][cp].y; v.y = acc[j][1][cp].y;
            v.z = acc[j][2][cp].y; v.w = acc[j][3][cp].y;
            *reinterpret_cast<float4*>(ob + (size_t)(2 * cp + 1) * L_LEN + 512 * j + 4 * t) = v;
        }
    }
}

extern "C" void kernel_launch(void* const* d_in, const int* in_sizes, int n_in,
                              void* d_out, int out_size)
{
    const float* x    = (const float*)d_in[0];  // (64, 8, 65536)
    const float* W    = (const float*)d_in[1];  // (8, 8, 4)
    const float* bias = (const float*)d_in[2];  // (8,)
    float* out        = (float*)d_out;          // (64, 8, 65536)

    // 64 batches * 64 position-chunks = 4096 blocks of 128
    conv_pbc_kernel<<<64 * (L_LEN / TILE), TPB>>>(x, W, bias, out);
}

// round 11
// speedup vs baseline: 2.2396x; 1.0774x over previous
#include <cuda_runtime.h>
#include <cstdint>

#define L_LEN   65536
#define L_MASK  (L_LEN - 1)
#define CIN     8
#define COUT    8
#define FS      4
#define TPB     128
#define TILE    1024       // positions per block (256 per warp)
#define ROWW    260        // per-warp row: 256 + 4 halo floats (16B-aligned)

// ---- packed f32x2 helpers (Blackwell sm_100a+) ------------------------------
__device__ __forceinline__ float2 ffma2(float2 a, float2 b, float2 c) {
    float2 d;
    asm("fma.rn.f32x2 %0, %1, %2, %3;"
        : "=l"(reinterpret_cast<unsigned long long&>(d))
        : "l"(reinterpret_cast<const unsigned long long&>(a)),
          "l"(reinterpret_cast<const unsigned long long&>(b)),
          "l"(reinterpret_cast<const unsigned long long&>(c)));
    return d;
}

__device__ __forceinline__ float2 dup2(float x) {
    float2 d;
    asm("mov.b64 %0, {%1, %1};"
        : "=l"(reinterpret_cast<unsigned long long&>(d))
        : "f"(x));
    return d;
}

// ----------------------------------------------------------------------------
// out[b, co, l] = bias[co] + sum_{ci,k} x[b, ci, (l+k) mod L] * W[co, ci, k]
//
// WARP-AUTONOMOUS version of the best kernel (R4): identical per-thread work
// (17 LDG.128 staging, 1024 FFMA2 monolithic compute), but each warp owns a
// private SMEM region (256 positions + 4 halo, all 8 ci) AND a private packed
// weight copy, synchronized ONLY by __syncwarp. No block barrier -> warps
// desynchronize, so staging latency of one warp overlaps FFMA2 of the others
// on the same SMSP instead of all warps stalling together.
// Lane owns bundles at 4*lid and 128+4*lid: conflict-free LDS.128 windows,
// warp-coalesced STG.128 stores. All 8 co as 4 f32x2-packed pairs.
// ----------------------------------------------------------------------------
__global__ __launch_bounds__(TPB, 4)
void conv_pbc_kernel(const float* __restrict__ x,
                     const float* __restrict__ W,
                     const float* __restrict__ bias,
                     float* __restrict__ out)
{
    __shared__ float  xs[4][CIN][ROWW];          // per-warp x regions
    __shared__ float2 w2s[4][CIN][FS][COUT / 2]; // per-warp weight copies
    __shared__ float2 b2s[4][COUT / 2];          // per-warp bias copies

    const int t   = threadIdx.x;
    const int w   = t >> 5;
    const int lid = t & 31;

    const int b    = blockIdx.x >> 6;                        // 64 chunks/batch
    const int base = ((blockIdx.x & 63) << 10) + (w << 8);   // warp's 256 pos

    const float* __restrict__ xb = x + (size_t)b * CIN * L_LEN;

    // ---- stage x: 16 coalesced LDG.128 + halo, all issued before any STS ----
    float4 va[CIN], vb[CIN], vh;
    #pragma unroll
    for (int ci = 0; ci < CIN; ++ci) {
        const float4* __restrict__ xc4 =
            reinterpret_cast<const float4*>(xb + (size_t)ci * L_LEN + base);
        va[ci] = xc4[lid];
        vb[ci] = xc4[lid + 32];
    }
    if (lid < CIN)   // halo: 4 floats past the warp region, circular, aligned
        vh = *reinterpret_cast<const float4*>(
            xb + (size_t)lid * L_LEN + ((base + 256) & L_MASK));

    #pragma unroll
    for (int ci = 0; ci < CIN; ++ci) {
        *reinterpret_cast<float4*>(&xs[w][ci][4 * lid])       = va[ci];
        *reinterpret_cast<float4*>(&xs[w][ci][128 + 4 * lid]) = vb[ci];
    }
    if (lid < CIN)
        *reinterpret_cast<float4*>(&xs[w][lid][256]) = vh;

    // ---- per-warp weights/bias (after x STS to keep the register peak) ----
    {
        const int ci = (lid >> 2) & 7;
        const int k  = lid & 3;
        #pragma unroll
        for (int cp = 0; cp < 4; ++cp)
            w2s[w][ci][k][cp] =
                make_float2(W[(2 * cp)     * CIN * FS + ci * FS + k],
                            W[(2 * cp + 1) * CIN * FS + ci * FS + k]);
        if (lid < COUT / 2)
            b2s[w][lid] = make_float2(bias[2 * lid], bias[2 * lid + 1]);
    }
    __syncwarp();                                // the ONLY sync in the kernel

    // ---- accumulators: acc[bundle][q][cp], init = bias ----
    float2 acc[2][4][COUT / 2];
    {
        const float2 c0 = b2s[w][0], c1 = b2s[w][1],
                     c2 = b2s[w][2], c3 = b2s[w][3];
        #pragma unroll
        for (int j = 0; j < 2; ++j)
            #pragma unroll
            for (int q = 0; q < 4; ++q) {
                acc[j][q][0] = c0; acc[j][q][1] = c1;
                acc[j][q][2] = c2; acc[j][q][3] = c3;
            }
    }

    // ---- monolithic compute from SMEM ----
    #pragma unroll
    for (int ci = 0; ci < CIN; ++ci) {
        float2 wv[FS][COUT / 2];
        #pragma unroll
        for (int k = 0; k < FS; ++k)
            #pragma unroll
            for (int cp = 0; cp < 4; ++cp)
                wv[k][cp] = w2s[w][ci][k][cp];

        float xw[2][8];
        {
            const float4 a0 = *reinterpret_cast<const float4*>(&xs[w][ci][4 * lid]);
            const float4 a1 = *reinterpret_cast<const float4*>(&xs[w][ci][4 * lid + 4]);
            const float4 b0 = *reinterpret_cast<const float4*>(&xs[w][ci][128 + 4 * lid]);
            const float4 b1 = *reinterpret_cast<const float4*>(&xs[w][ci][128 + 4 * lid + 4]);
            xw[0][0] = a0.x; xw[0][1] = a0.y; xw[0][2] = a0.z; xw[0][3] = a0.w;
            xw[0][4] = a1.x; xw[0][5] = a1.y; xw[0][6] = a1.z; xw[0][7] = a1.w;
            xw[1][0] = b0.x; xw[1][1] = b0.y; xw[1][2] = b0.z; xw[1][3] = b0.w;
            xw[1][4] = b1.x; xw[1][5] = b1.y; xw[1][6] = b1.z; xw[1][7] = b1.w;
        }

        #pragma unroll
        for (int j = 0; j < 2; ++j) {
            #pragma unroll
            for (int i = 0; i < 7; ++i) {
                const float2 xk = dup2(xw[j][i]);
                #pragma unroll
                for (int k = 0; k < FS; ++k) {
                    const int q = i - k;
                    if (q >= 0 && q < 4) {
                        #pragma unroll
                        for (int cp = 0; cp < 4; ++cp)
                            acc[j][q][cp] = ffma2(wv[k][cp], xk, acc[j][q][cp]);
                    }
                }
            }
        }
    }

    // ---- epilogue: warp-coalesced STG.128 per (co, bundle) ----
    float* __restrict__ ob = out + (size_t)b * COUT * L_LEN + base + 4 * lid;
    #pragma unroll
    for (int cp = 0; cp < 4; ++cp) {
        #pragma unroll
        for (int j = 0; j < 2; ++j) {
            float4 v;
            v.x = acc[j][0][cp].x; v.y = acc[j][1][cp].x;
            v.z = acc[j][2][cp].x; v.w = acc[j][3][cp].x;
            *reinterpret_cast<float4*>(ob + (size_t)(2 * cp) * L_LEN + 128 * j) = v;
            v.x = acc[j][0][cp].y; v.y = acc[j][1][cp].y;
            v.z = acc[j][2][cp].y; v.w = acc[j][3][cp].y;
            *reinterpret_cast<float4*>(ob + (size_t)(2 * cp + 1) * L_LEN + 128 * j) = v;
        }
    }
}

extern "C" void kernel_launch(void* const* d_in, const int* in_sizes, int n_in,
                              void* d_out, int out_size)
{
    const float* x    = (const float*)d_in[0];  // (64, 8, 65536)
    const float* W    = (const float*)d_in[1];  // (8, 8, 4)
    const float* bias = (const float*)d_in[2];  // (8,)
    float* out        = (float*)d_out;          // (64, 8, 65536)

    // 64 batches * 64 chunks (1024 positions, 256 per warp) = 4096 blocks
    conv_pbc_kernel<<<64 * (L_LEN / TILE), TPB>>>(x, W, bias, out);
}